// round 6
// baseline (speedup 1.0000x reference)
#include <cuda_runtime.h>
#include <cuda_bf16.h>
#include <math.h>
#include <cstdint>

// ---------------- problem constants ----------------
#define SQ     2048
#define HID    2048
#define VOC    32000
#define NHEAD  16
#define NKVH   4
#define HDIM   128
#define FFD    8192
#define NLAYER 4
#define NQKV   3072   // 2048 + 512 + 512

#define SH  (SQ * HID)
#define SFF (SQ * FFD)

// hbuf SH + qkv SQ*NQKV + gbuf SFF + ubuf SFF + bpack 4096
__device__ float g_scratch[(size_t)SH + (size_t)SQ * NQKV + 2 * (size_t)SFF + 4096];
__device__ __nv_bfloat16 g_ahi[(size_t)SFF];
__device__ __nv_bfloat16 g_alo[(size_t)SFF];
__device__ __nv_bfloat16 g_whi[(size_t)HID * VOC];
__device__ __nv_bfloat16 g_wlo[(size_t)HID * VOC];

// ======================= helpers =======================
__device__ __forceinline__ uint32_t smem_u32(const void* p) {
    uint32_t a;
    asm("{ .reg .u64 t; cvta.to.shared.u64 t, %1; cvt.u32.u64 %0, t; }"
        : "=r"(a) : "l"(p));
    return a;
}
__device__ __forceinline__ void ldsm_x4(uint32_t* r, uint32_t addr) {
    asm volatile("ldmatrix.sync.aligned.m8n8.x4.shared.b16 {%0,%1,%2,%3}, [%4];"
                 : "=r"(r[0]), "=r"(r[1]), "=r"(r[2]), "=r"(r[3]) : "r"(addr));
}
__device__ __forceinline__ void ldsm_x4t(uint32_t* r, uint32_t addr) {
    asm volatile("ldmatrix.sync.aligned.m8n8.x4.trans.shared.b16 {%0,%1,%2,%3}, [%4];"
                 : "=r"(r[0]), "=r"(r[1]), "=r"(r[2]), "=r"(r[3]) : "r"(addr));
}
__device__ __forceinline__ void mma_bf16(float* c, const uint32_t* a,
                                         const uint32_t* b) {
    asm volatile("mma.sync.aligned.m16n8k16.row.col.f32.bf16.bf16.f32 "
                 "{%0,%1,%2,%3}, {%4,%5,%6,%7}, {%8,%9}, {%0,%1,%2,%3};"
                 : "+f"(c[0]), "+f"(c[1]), "+f"(c[2]), "+f"(c[3])
                 : "r"(a[0]), "r"(a[1]), "r"(a[2]), "r"(a[3]),
                   "r"(b[0]), "r"(b[1]));
}
__device__ __forceinline__ uint32_t pack2(__nv_bfloat16 a, __nv_bfloat16 b) {
    uint16_t ua = *(uint16_t*)&a, ub = *(uint16_t*)&b;
    return ((uint32_t)ub << 16) | (uint32_t)ua;
}
__device__ __forceinline__ void split4(float4 f, uint2& hi, uint2& lo) {
    __nv_bfloat16 hx = __float2bfloat16_rn(f.x);
    __nv_bfloat16 hy = __float2bfloat16_rn(f.y);
    __nv_bfloat16 hz = __float2bfloat16_rn(f.z);
    __nv_bfloat16 hw = __float2bfloat16_rn(f.w);
    __nv_bfloat16 lx = __float2bfloat16_rn(f.x - __bfloat162float(hx));
    __nv_bfloat16 ly = __float2bfloat16_rn(f.y - __bfloat162float(hy));
    __nv_bfloat16 lz = __float2bfloat16_rn(f.z - __bfloat162float(hz));
    __nv_bfloat16 lw = __float2bfloat16_rn(f.w - __bfloat162float(hw));
    hi = make_uint2(pack2(hx, hy), pack2(hz, hw));
    lo = make_uint2(pack2(lx, ly), pack2(lz, lw));
}
#define CP16(dst, src) \
    asm volatile("cp.async.cg.shared.global [%0], [%1], 16;" :: "r"(dst), "l"(src))
#define CP_COMMIT() asm volatile("cp.async.commit_group;" ::: "memory")

// ---------------- weight splits ----------------
__global__ void split_kernel(const float* __restrict__ src,
                             __nv_bfloat16* __restrict__ hi,
                             __nv_bfloat16* __restrict__ lo, int n4) {
    int i = blockIdx.x * blockDim.x + threadIdx.x;
    if (i >= n4) return;
    uint2 h, l;
    split4(((const float4*)src)[i], h, l);
    ((uint2*)hi)[i] = h;
    ((uint2*)lo)[i] = l;
}
// src is [K, n] contiguous; dst planes have row stride ld (elements), dst
// pointers already offset to the first column.
__global__ void split2d_kernel(const float* __restrict__ src,
                               __nv_bfloat16* __restrict__ hi,
                               __nv_bfloat16* __restrict__ lo,
                               int n4row, int ld4, int total4) {
    int i = blockIdx.x * blockDim.x + threadIdx.x;
    if (i >= total4) return;
    int r = i / n4row, c = i % n4row;
    uint2 h, l;
    split4(((const float4*)src)[i], h, l);
    ((uint2*)hi)[(size_t)r * ld4 + c] = h;
    ((uint2*)lo)[(size_t)r * ld4 + c] = l;
}

// ======================= pre-split bf16x3 GEMM (multistage cp.async) =======================
// C[M,N] = A[M,K] @ W[K,N] (+bias)(+res). BM=256, BN=128, BK=32, 512 thr, 3 stages.
#define BM     256
#define NSTAGE 3
#define ST_A_LO (BM * 80u)
#define ST_B_HI (2u * BM * 80u)
#define ST_B_LO (ST_B_HI + 9728u)
#define STAGEB  (ST_B_LO + 9728u)
#define GEMM_SMEM (NSTAGE * STAGEB)

__global__ __launch_bounds__(512, 1)
void gemm_ps_kernel(const __nv_bfloat16* __restrict__ Ahi,
                    const __nv_bfloat16* __restrict__ Alo,
                    const __nv_bfloat16* __restrict__ Whi,
                    const __nv_bfloat16* __restrict__ Wlo,
                    const float* __restrict__ bias, const float* __restrict__ res,
                    float* __restrict__ C, int M, int N, int K) {
    extern __shared__ char sm[];
    const uint32_t smb = smem_u32(sm);
    const int tid  = threadIdx.x;
    const int lane = tid & 31;
    const int warp = tid >> 5;
    const int wm = warp & 7;      // 8 warps over M (32 rows each)
    const int wn = warp >> 3;     // 2 warps over N (64 cols each)
    const int bm = blockIdx.y * BM;
    const int bn = blockIdx.x * 128;

    const uint32_t aLd = (uint32_t)((wm * 32 + (lane & 15)) * 80 +
                                    ((lane >> 4) & 1) * 16);
    const uint32_t bLd = (uint32_t)((lane & 15) * 304 + (lane >> 4) * 16 +
                                    wn * 128);

    float acc[2][8][4];
#pragma unroll
    for (int i = 0; i < 2; i++)
#pragma unroll
        for (int j = 0; j < 8; j++)
#pragma unroll
            for (int q = 0; q < 4; q++) acc[i][j][q] = 0.f;

    const int nc = K >> 5;

    auto issue = [&](int c, int stg) {
        if (c < nc) {
            const uint32_t st = smb + (uint32_t)stg * STAGEB;
            const size_t kof = (size_t)c * 32;
            {   // A: 256 rows x 32 cols, 512 threads -> 1 x 16B per plane
                int r = tid >> 1, cc = tid & 1;
                uint32_t d = st + (uint32_t)(r * 80 + cc * 16);
                size_t so = (size_t)(bm + r) * K + kof + cc * 8 + (tid & 0) ;
                // each thread covers 8 halves; two threads per row cover 16 of 32
                // second 16 halves handled by offset below
                CP16(d, Ahi + so);
                CP16(d + ST_A_LO, Alo + so);
                uint32_t d2 = d + 32u;
                size_t so2 = so + 16;
                CP16(d2, Ahi + so2);
                CP16(d2 + ST_A_LO, Alo + so2);
            }
            {   // B: 32 k-rows x 128 cols
                int kr = tid >> 4, ncc = tid & 15;
                uint32_t d = st + ST_B_HI + (uint32_t)(kr * 304 + ncc * 16);
                size_t so = (size_t)(kof + kr) * N + bn + ncc * 8;
                CP16(d, Whi + so);
                CP16(d + 9728u, Wlo + so);
            }
        }
        CP_COMMIT();
    };

#pragma unroll
    for (int s = 0; s < NSTAGE - 1; s++) issue(s, s);

    for (int c = 0; c < nc; c++) {
        asm volatile("cp.async.wait_group %0;" :: "n"(NSTAGE - 2) : "memory");
        __syncthreads();
        issue(c + NSTAGE - 1, (c + NSTAGE - 1) % NSTAGE);
        const uint32_t sb = smb + (uint32_t)(c % NSTAGE) * STAGEB;
#pragma unroll
        for (int ks = 0; ks < 2; ks++) {
            uint32_t ah[2][4], al[2][4];
#pragma unroll
            for (int tm = 0; tm < 2; tm++) {
                uint32_t off = aLd + (uint32_t)(tm * 16 * 80 + ks * 32);
                ldsm_x4(ah[tm], sb + off);
                ldsm_x4(al[tm], sb + ST_A_LO + off);
            }
#pragma unroll
            for (int p = 0; p < 4; p++) {
                uint32_t off = bLd + (uint32_t)(ks * 16 * 304 + p * 32);
                uint32_t bh[4], bl[4];
                ldsm_x4t(bh, sb + ST_B_HI + off);
                ldsm_x4t(bl, sb + ST_B_LO + off);
#pragma unroll
                for (int h = 0; h < 2; h++) {
#pragma unroll
                    for (int tm = 0; tm < 2; tm++) {
                        mma_bf16(acc[tm][p * 2 + h], ah[tm], bh + 2 * h);
                        mma_bf16(acc[tm][p * 2 + h], ah[tm], bl + 2 * h);
                        mma_bf16(acc[tm][p * 2 + h], al[tm], bh + 2 * h);
                    }
                }
            }
        }
    }

    // ---- epilogue ----
#pragma unroll
    for (int tm = 0; tm < 2; tm++) {
#pragma unroll
        for (int bt = 0; bt < 8; bt++) {
            int r0  = bm + wm * 32 + tm * 16 + (lane >> 2);
            int col = bn + wn * 64 + bt * 8 + (lane & 3) * 2;
            float2 v0 = make_float2(acc[tm][bt][0], acc[tm][bt][1]);
            float2 v1 = make_float2(acc[tm][bt][2], acc[tm][bt][3]);
            if (bias) {
                float2 bb = *(const float2*)(bias + col);
                v0.x += bb.x; v0.y += bb.y;
                v1.x += bb.x; v1.y += bb.y;
            }
            if (res) {
                float2 r0v = *(const float2*)(res + (size_t)r0 * N + col);
                float2 r1v = *(const float2*)(res + (size_t)(r0 + 8) * N + col);
                v0.x += r0v.x; v0.y += r0v.y;
                v1.x += r1v.x; v1.y += r1v.y;
            }
            *(float2*)(C + (size_t)r0 * N + col) = v0;
            *(float2*)(C + (size_t)(r0 + 8) * N + col) = v1;
        }
    }
}

// ---------------- embedding gather ----------------
__global__ void embed_kernel(const int* __restrict__ ids,
                             const float* __restrict__ emb,
                             float* __restrict__ h) {
    int i = blockIdx.x * blockDim.x + threadIdx.x;
    int s = i / (HID / 4);
    int c = i % (HID / 4);
    int tok = ids[s];
    float4 v = ((const float4*)(emb + (size_t)tok * HID))[c];
    ((float4*)(h + (size_t)s * HID))[c] = v;
}

// ---------------- RMSNorm -> bf16 hi/lo planes ----------------
__global__ void rmsnorm_split_kernel(const float* __restrict__ x,
                                     const float* __restrict__ w,
                                     __nv_bfloat16* __restrict__ hi,
                                     __nv_bfloat16* __restrict__ lo) {
    int row = blockIdx.x;
    const float4* xr = (const float4*)(x + (size_t)row * HID);
    const float4* wr = (const float4*)w;

    float4 v0 = xr[threadIdx.x];
    float4 v1 = xr[threadIdx.x + 256];
    float ss = v0.x * v0.x + v0.y * v0.y + v0.z * v0.z + v0.w * v0.w
             + v1.x * v1.x + v1.y * v1.y + v1.z * v1.z + v1.w * v1.w;

    __shared__ float red[8];
    for (int o = 16; o > 0; o >>= 1) ss += __shfl_down_sync(0xffffffffu, ss, o);
    if ((threadIdx.x & 31) == 0) red[threadIdx.x >> 5] = ss;
    __syncthreads();
    if (threadIdx.x < 8) {
        float t = red[threadIdx.x];
        for (int o = 4; o > 0; o >>= 1) t += __shfl_down_sync(0xffu, t, o);
        if (threadIdx.x == 0) red[0] = t;
    }
    __syncthreads();
    float inv = rsqrtf(red[0] / (float)HID + 1e-6f);

    float4 w0 = wr[threadIdx.x];
    float4 w1 = wr[threadIdx.x + 256];
    float4 o0, o1;
    o0.x = v0.x * inv * w0.x; o0.y = v0.y * inv * w0.y;
    o0.z = v0.z * inv * w0.z; o0.w = v0.w * inv * w0.w;
    o1.x = v1.x * inv * w1.x; o1.y = v1.y * inv * w1.y;
    o1.z = v1.z * inv * w1.z; o1.w = v1.w * inv * w1.w;
    uint2 h, l;
    size_t b = (size_t)row * (HID / 4);
    split4(o0, h, l);
    ((uint2*)hi)[b + threadIdx.x] = h;
    ((uint2*)lo)[b + threadIdx.x] = l;
    split4(o1, h, l);
    ((uint2*)hi)[b + threadIdx.x + 256] = h;
    ((uint2*)lo)[b + threadIdx.x + 256] = l;
}

// ---------------- RoPE (in place on packed qkv) ----------------
__global__ void rope_kernel(float* __restrict__ qkv) {
    int s = blockIdx.x;
    int hh = blockIdx.y;   // 0..19 : 16 q heads then 4 k heads
    int i = threadIdx.x;
    float inv = powf(1000000.0f, -(float)i / 64.0f);
    float f = (float)s * inv;
    float c = cosf(f), sn = sinf(f);
    float* base = qkv + (size_t)s * NQKV +
                  ((hh < NHEAD) ? hh * HDIM : HID + (hh - NHEAD) * HDIM);
    float x1 = base[i];
    float x2 = base[i + 64];
    base[i]      = x1 * c - x2 * sn;
    base[i + 64] = x2 * c + x1 * sn;
}

// ---------------- flash attention (fp32 SIMT, causal, GQA), split output ----------------
#define LDQ 132
#define ATTN_SMEM ((3 * 64 * LDQ + 64 * 65 + 3 * 64) * 4)

__global__ __launch_bounds__(256) void attn_kernel(
    const float* __restrict__ q, const float* __restrict__ k,
    const float* __restrict__ v,
    __nv_bfloat16* __restrict__ ohi, __nv_bfloat16* __restrict__ olo) {
    extern __shared__ float smf[];
    float* Qs   = smf;
    float* Ks   = Qs + 64 * LDQ;
    float* Vs   = Ks + 64 * LDQ;
    float* Ss   = Vs + 64 * LDQ;
    float* Mrow = Ss + 64 * 65;
    float* Lrow = Mrow + 64;
    float* Arow = Lrow + 64;

    const int head = blockIdx.x;
    const int qb   = blockIdx.y;
    const int kvh  = head >> 2;
    const int tid  = threadIdx.x;

    for (int i = tid; i < 64 * 32; i += 256) {
        int r = i >> 5, c4 = (i & 31) << 2;
        *(float4*)(Qs + r * LDQ + c4) =
            *(const float4*)(q + (size_t)(qb * 64 + r) * NQKV + head * HDIM + c4);
    }
    if (tid < 64) { Mrow[tid] = -1e30f; Lrow[tid] = 0.f; }

    float acc[4][8];
#pragma unroll
    for (int i = 0; i < 4; i++)
#pragma unroll
        for (int j = 0; j < 8; j++) acc[i][j] = 0.f;

    const int i0 = (tid >> 4) * 4;
    const int j0 = (tid & 15) * 4;
    const int d0 = (tid & 15) * 8;
    const float scale = 0.08838834764831845f;

    for (int kb = 0; kb <= qb; kb++) {
        __syncthreads();
        for (int i = tid; i < 64 * 32; i += 256) {
            int r = i >> 5, c4 = (i & 31) << 2;
            size_t off = (size_t)(kb * 64 + r) * NQKV + kvh * HDIM + c4;
            *(float4*)(Ks + r * LDQ + c4) = *(const float4*)(k + off);
            *(float4*)(Vs + r * LDQ + c4) = *(const float4*)(v + off);
        }
        __syncthreads();

        float sc[4][4];
#pragma unroll
        for (int a = 0; a < 4; a++)
#pragma unroll
            for (int b = 0; b < 4; b++) sc[a][b] = 0.f;
        for (int d4 = 0; d4 < HDIM; d4 += 4) {
            float4 qv[4], kv[4];
#pragma unroll
            for (int a = 0; a < 4; a++) qv[a] = *(const float4*)(Qs + (i0 + a) * LDQ + d4);
#pragma unroll
            for (int b = 0; b < 4; b++) kv[b] = *(const float4*)(Ks + (j0 + b) * LDQ + d4);
#pragma unroll
            for (int a = 0; a < 4; a++)
#pragma unroll
                for (int b = 0; b < 4; b++)
                    sc[a][b] += qv[a].x * kv[b].x + qv[a].y * kv[b].y
                              + qv[a].z * kv[b].z + qv[a].w * kv[b].w;
        }
#pragma unroll
        for (int a = 0; a < 4; a++)
#pragma unroll
            for (int b = 0; b < 4; b++) {
                float val = sc[a][b] * scale;
                if (kb == qb && (j0 + b) > (i0 + a)) val = -1e9f;
                Ss[(i0 + a) * 65 + (j0 + b)] = val;
            }
        __syncthreads();

        if (tid < 64) {
            int i = tid;
            float m = Mrow[i];
            float mb = -1e30f;
            for (int j = 0; j < 64; j++) mb = fmaxf(mb, Ss[i * 65 + j]);
            float mn = fmaxf(m, mb);
            float a = expf(m - mn);
            float s = 0.f;
            for (int j = 0; j < 64; j++) {
                float p = expf(Ss[i * 65 + j] - mn);
                Ss[i * 65 + j] = p;
                s += p;
            }
            Lrow[i] = Lrow[i] * a + s;
            Mrow[i] = mn;
            Arow[i] = a;
        }
        __syncthreads();

#pragma unroll
        for (int a = 0; a < 4; a++) {
            float al = Arow[i0 + a];
#pragma unroll
            for (int d = 0; d < 8; d++) acc[a][d] *= al;
        }
        for (int j = 0; j < 64; j++) {
            float4 v0 = *(const float4*)(Vs + j * LDQ + d0);
            float4 v1 = *(const float4*)(Vs + j * LDQ + d0 + 4);
#pragma unroll
            for (int a = 0; a < 4; a++) {
                float p = Ss[(i0 + a) * 65 + j];
                acc[a][0] += p * v0.x; acc[a][1] += p * v0.y;
                acc[a][2] += p * v0.z; acc[a][3] += p * v0.w;
                acc[a][4] += p * v1.x; acc[a][5] += p * v1.y;
                acc[a][6] += p * v1.z; acc[a][7] += p * v1.w;
            }
        }
    }

#pragma unroll
    for (int a = 0; a < 4; a++) {
        float linv = 1.0f / Lrow[i0 + a];
        int row = qb * 64 + i0 + a;
        float4 o0, o1;
        o0.x = acc[a][0] * linv; o0.y = acc[a][1] * linv;
        o0.z = acc[a][2] * linv; o0.w = acc[a][3] * linv;
        o1.x = acc[a][4] * linv; o1.y = acc[a][5] * linv;
        o1.z = acc[a][6] * linv; o1.w = acc[a][7] * linv;
        size_t b4 = ((size_t)row * HID + head * HDIM + d0) >> 2;
        uint2 h, l;
        split4(o0, h, l);
        ((uint2*)ohi)[b4] = h;
        ((uint2*)olo)[b4] = l;
        split4(o1, h, l);
        ((uint2*)ohi)[b4 + 1] = h;
        ((uint2*)olo)[b4 + 1] = l;
    }
}

// ---------------- SiLU(g) * u -> bf16 hi/lo planes ----------------
__global__ void silu_split_kernel(const float* __restrict__ g,
                                  const float* __restrict__ u,
                                  __nv_bfloat16* __restrict__ hi,
                                  __nv_bfloat16* __restrict__ lo) {
    int i = blockIdx.x * blockDim.x + threadIdx.x;
    float4 gv = ((const float4*)g)[i];
    float4 uv = ((const float4*)u)[i];
    gv.x = gv.x / (1.f + expf(-gv.x)) * uv.x;
    gv.y = gv.y / (1.f + expf(-gv.y)) * uv.y;
    gv.z = gv.z / (1.f + expf(-gv.z)) * uv.z;
    gv.w = gv.w / (1.f + expf(-gv.w)) * uv.w;
    uint2 h, l;
    split4(gv, h, l);
    ((uint2*)hi)[i] = h;
    ((uint2*)lo)[i] = l;
}

// ---------------- host orchestration ----------------
static __nv_bfloat16 *s_ahi, *s_alo, *s_whi, *s_wlo;

static void run_split(const float* src, size_t n) {
    int n4 = (int)(n / 4);
    split_kernel<<<(n4 + 255) / 256, 256>>>(src, s_whi, s_wlo, n4);
}
static void run_split2d(const float* src, int n, int coloff) {
    int total4 = (int)((size_t)HID * n / 4);
    split2d_kernel<<<(total4 + 255) / 256, 256>>>(
        src, s_whi + coloff, s_wlo + coloff, n / 4, NQKV / 4, total4);
}
static void run_gemm(const float* bias, const float* res, float* C,
                     int M, int N, int K) {
    dim3 grid(N / 128, M / BM);
    gemm_ps_kernel<<<grid, 512, GEMM_SMEM>>>(
        s_ahi, s_alo, s_whi, s_wlo, bias, res, C, M, N, K);
}

extern "C" void kernel_launch(void* const* d_in, const int* in_sizes, int n_in,
                              void* d_out, int out_size) {
    const int*   ids    = (const int*)d_in[0];
    const float* emb    = (const float*)d_in[1];
    const float* Wq     = (const float*)d_in[2];
    const float* bq     = (const float*)d_in[3];
    const float* Wk     = (const float*)d_in[4];
    const float* bk     = (const float*)d_in[5];
    const float* Wv     = (const float*)d_in[6];
    const float* bv     = (const float*)d_in[7];
    const float* Wo     = (const float*)d_in[8];
    const float* ln1    = (const float*)d_in[9];
    const float* ln2    = (const float*)d_in[10];
    const float* Wg     = (const float*)d_in[11];
    const float* Wu     = (const float*)d_in[12];
    const float* Wd     = (const float*)d_in[13];
    const float* norm_w = (const float*)d_in[14];
    const float* Wlm    = (const float*)d_in[15];
    const float* blm    = (const float*)d_in[16];
    float* out = (float*)d_out;

    float* base = nullptr;
    cudaGetSymbolAddress((void**)&base, g_scratch);
    cudaGetSymbolAddress((void**)&s_ahi, g_ahi);
    cudaGetSymbolAddress((void**)&s_alo, g_alo);
    cudaGetSymbolAddress((void**)&s_whi, g_whi);
    cudaGetSymbolAddress((void**)&s_wlo, g_wlo);

    float* hbuf  = base;
    float* qkv   = base + (size_t)SH;
    float* gbuf  = qkv + (size_t)SQ * NQKV;
    float* ubuf  = gbuf + (size_t)SFF;
    float* bpack = ubuf + (size_t)SFF;

    cudaFuncSetAttribute(attn_kernel, cudaFuncAttributeMaxDynamicSharedMemorySize,
                         ATTN_SMEM);
    cudaFuncSetAttribute(gemm_ps_kernel,
                         cudaFuncAttributeMaxDynamicSharedMemorySize, GEMM_SMEM);

    embed_kernel<<<SH / 4 / 256, 256>>>(ids, emb, hbuf);

    for (int l = 0; l < NLAYER; l++) {
        const float* Wql = Wq + (size_t)l * HID * HID;
        const float* bql = bq + (size_t)l * HID;
        const float* Wkl = Wk + (size_t)l * HID * (NKVH * HDIM);
        const float* bkl = bk + (size_t)l * (NKVH * HDIM);
        const float* Wvl = Wv + (size_t)l * HID * (NKVH * HDIM);
        const float* bvl = bv + (size_t)l * (NKVH * HDIM);
        const float* Wol = Wo + (size_t)l * HID * HID;
        const float* l1  = ln1 + (size_t)l * HID;
        const float* l2  = ln2 + (size_t)l * HID;
        const float* Wgl = Wg + (size_t)l * HID * FFD;
        const float* Wul = Wu + (size_t)l * HID * FFD;
        const float* Wdl = Wd + (size_t)l * FFD * HID;

        // fused QKV projection
        rmsnorm_split_kernel<<<SQ, 256>>>(hbuf, l1, s_ahi, s_alo);
        cudaMemcpyAsync(bpack, bql, HID * sizeof(float),
                        cudaMemcpyDeviceToDevice);
        cudaMemcpyAsync(bpack + HID, bkl, NKVH * HDIM * sizeof(float),
                        cudaMemcpyDeviceToDevice);
        cudaMemcpyAsync(bpack + HID + NKVH * HDIM, bvl,
                        NKVH * HDIM * sizeof(float), cudaMemcpyDeviceToDevice);
        run_split2d(Wql, HID, 0);
        run_split2d(Wkl, NKVH * HDIM, HID);
        run_split2d(Wvl, NKVH * HDIM, HID + NKVH * HDIM);
        run_gemm(bpack, nullptr, qkv, SQ, NQKV, HID);

        dim3 rgrid(SQ, NHEAD + NKVH);
        rope_kernel<<<rgrid, 64>>>(qkv);

        dim3 agrid(NHEAD, SQ / 64);
        attn_kernel<<<agrid, 256, ATTN_SMEM>>>(qkv, qkv + HID,
                                               qkv + HID + NKVH * HDIM,
                                               s_ahi, s_alo);

        run_split(Wol, (size_t)HID * HID);
        run_gemm(nullptr, hbuf, hbuf, SQ, HID, HID);

        rmsnorm_split_kernel<<<SQ, 256>>>(hbuf, l2, s_ahi, s_alo);
        run_split(Wgl, (size_t)HID * FFD);
        run_gemm(nullptr, nullptr, gbuf, SQ, FFD, HID);
        run_split(Wul, (size_t)HID * FFD);
        run_gemm(nullptr, nullptr, ubuf, SQ, FFD, HID);
        silu_split_kernel<<<SFF / 4 / 256, 256>>>(gbuf, ubuf, s_ahi, s_alo);
        run_split(Wdl, (size_t)FFD * HID);
        run_gemm(nullptr, hbuf, hbuf, SQ, HID, FFD);
    }

    rmsnorm_split_kernel<<<SQ, 256>>>(hbuf, norm_w, s_ahi, s_alo);
    run_split(Wlm, (size_t)HID * VOC);
    run_gemm(blm, nullptr, out, SQ, VOC, HID);
}

// round 7
// speedup vs baseline: 1.0998x; 1.0998x over previous
#include <cuda_runtime.h>
#include <cuda_bf16.h>
#include <math.h>
#include <cstdint>

// ---------------- problem constants ----------------
#define SQ     2048
#define HID    2048
#define VOC    32000
#define NHEAD  16
#define NKVH   4
#define HDIM   128
#define FFD    8192
#define NLAYER 4
#define NQKV   3072   // 2048 + 512 + 512

#define SH  (SQ * HID)
#define SFF (SQ * FFD)

// hbuf SH + qkv SQ*NQKV + gbuf SFF + ubuf SFF + bpack 4096
__device__ float g_scratch[(size_t)SH + (size_t)SQ * NQKV + 2 * (size_t)SFF + 4096];
__device__ __nv_bfloat16 g_ahi[(size_t)SFF];
__device__ __nv_bfloat16 g_alo[(size_t)SFF];
__device__ __nv_bfloat16 g_whi[(size_t)HID * VOC];
__device__ __nv_bfloat16 g_wlo[(size_t)HID * VOC];

// ======================= helpers =======================
__device__ __forceinline__ uint32_t smem_u32(const void* p) {
    uint32_t a;
    asm("{ .reg .u64 t; cvta.to.shared.u64 t, %1; cvt.u32.u64 %0, t; }"
        : "=r"(a) : "l"(p));
    return a;
}
__device__ __forceinline__ void ldsm_x4(uint32_t* r, uint32_t addr) {
    asm volatile("ldmatrix.sync.aligned.m8n8.x4.shared.b16 {%0,%1,%2,%3}, [%4];"
                 : "=r"(r[0]), "=r"(r[1]), "=r"(r[2]), "=r"(r[3]) : "r"(addr));
}
__device__ __forceinline__ void ldsm_x4t(uint32_t* r, uint32_t addr) {
    asm volatile("ldmatrix.sync.aligned.m8n8.x4.trans.shared.b16 {%0,%1,%2,%3}, [%4];"
                 : "=r"(r[0]), "=r"(r[1]), "=r"(r[2]), "=r"(r[3]) : "r"(addr));
}
__device__ __forceinline__ void mma_bf16(float* c, const uint32_t* a,
                                         const uint32_t* b) {
    asm volatile("mma.sync.aligned.m16n8k16.row.col.f32.bf16.bf16.f32 "
                 "{%0,%1,%2,%3}, {%4,%5,%6,%7}, {%8,%9}, {%0,%1,%2,%3};"
                 : "+f"(c[0]), "+f"(c[1]), "+f"(c[2]), "+f"(c[3])
                 : "r"(a[0]), "r"(a[1]), "r"(a[2]), "r"(a[3]),
                   "r"(b[0]), "r"(b[1]));
}
__device__ __forceinline__ uint32_t pack2(__nv_bfloat16 a, __nv_bfloat16 b) {
    uint16_t ua = *(uint16_t*)&a, ub = *(uint16_t*)&b;
    return ((uint32_t)ub << 16) | (uint32_t)ua;
}
__device__ __forceinline__ void split4(float4 f, uint2& hi, uint2& lo) {
    __nv_bfloat16 hx = __float2bfloat16_rn(f.x);
    __nv_bfloat16 hy = __float2bfloat16_rn(f.y);
    __nv_bfloat16 hz = __float2bfloat16_rn(f.z);
    __nv_bfloat16 hw = __float2bfloat16_rn(f.w);
    __nv_bfloat16 lx = __float2bfloat16_rn(f.x - __bfloat162float(hx));
    __nv_bfloat16 ly = __float2bfloat16_rn(f.y - __bfloat162float(hy));
    __nv_bfloat16 lz = __float2bfloat16_rn(f.z - __bfloat162float(hz));
    __nv_bfloat16 lw = __float2bfloat16_rn(f.w - __bfloat162float(hw));
    hi = make_uint2(pack2(hx, hy), pack2(hz, hw));
    lo = make_uint2(pack2(lx, ly), pack2(lz, lw));
}
#define CP16(dst, src) \
    asm volatile("cp.async.cg.shared.global [%0], [%1], 16;" :: "r"(dst), "l"(src))
#define CP_COMMIT() asm volatile("cp.async.commit_group;" ::: "memory")

// ---------------- weight splits ----------------
__global__ void split_kernel(const float* __restrict__ src,
                             __nv_bfloat16* __restrict__ hi,
                             __nv_bfloat16* __restrict__ lo, int n4) {
    int i = blockIdx.x * blockDim.x + threadIdx.x;
    if (i >= n4) return;
    uint2 h, l;
    split4(((const float4*)src)[i], h, l);
    ((uint2*)hi)[i] = h;
    ((uint2*)lo)[i] = l;
}
// src is [K, n] contiguous; planes have row stride ld4*4; dst offset prebaked.
__global__ void split2d_kernel(const float* __restrict__ src,
                               __nv_bfloat16* __restrict__ hi,
                               __nv_bfloat16* __restrict__ lo,
                               int n4row, int ld4, int total4) {
    int i = blockIdx.x * blockDim.x + threadIdx.x;
    if (i >= total4) return;
    int r = i / n4row, c = i % n4row;
    uint2 h, l;
    split4(((const float4*)src)[i], h, l);
    ((uint2*)hi)[(size_t)r * ld4 + c] = h;
    ((uint2*)lo)[(size_t)r * ld4 + c] = l;
}
// merged K+V split into qkv weight planes at column offset HID
__global__ void splitkv_kernel(const float* __restrict__ Wk,
                               const float* __restrict__ Wv,
                               __nv_bfloat16* __restrict__ hi,
                               __nv_bfloat16* __restrict__ lo) {
    int i = blockIdx.x * blockDim.x + threadIdx.x;   // over HID * 1024 / 4
    if (i >= HID * 1024 / 4) return;
    int r = i >> 8;             // K row
    int c4 = i & 255;           // 0..255 -> col 4*c4 in [0,1024)
    const float* src = (c4 < 128) ? Wk + (size_t)r * 512 + c4 * 4
                                  : Wv + (size_t)r * 512 + (c4 - 128) * 4;
    uint2 h, l;
    split4(*(const float4*)src, h, l);
    size_t o = (size_t)r * (NQKV / 4) + (HID / 4) + c4;
    ((uint2*)hi)[o] = h;
    ((uint2*)lo)[o] = l;
}
// pack bq|bk|bv -> bpack[3072]
__global__ void biaspack_kernel(const float* __restrict__ bq,
                                const float* __restrict__ bk,
                                const float* __restrict__ bv,
                                float* __restrict__ bp) {
    int i = blockIdx.x * blockDim.x + threadIdx.x;
    if (i >= NQKV) return;
    bp[i] = (i < HID) ? bq[i]
          : (i < HID + 512) ? bk[i - HID] : bv[i - HID - 512];
}

// ======================= pre-split bf16x3 GEMM (cp.async, R5-proven pipeline) =======================
// C[M,N] = A[M,K] @ W[K,N] (+bias)(+res). BN=128, BK=32. BM template (128/256).
template<int BM, int NSTAGE>
__global__ __launch_bounds__(BM * 2, (BM == 128) ? 2 : 1)
void gemm_ps_kernel(const __nv_bfloat16* __restrict__ Ahi,
                    const __nv_bfloat16* __restrict__ Alo,
                    const __nv_bfloat16* __restrict__ Whi,
                    const __nv_bfloat16* __restrict__ Wlo,
                    const float* __restrict__ bias, const float* __restrict__ res,
                    float* __restrict__ C, int M, int N, int K) {
    constexpr int NTHR = BM * 2;
    constexpr int NWM  = BM / 32;
    constexpr uint32_t ST_A_LO = (uint32_t)BM * 80u;
    constexpr uint32_t ST_B_HI = 2u * BM * 80u;
    constexpr uint32_t ST_B_LO = ST_B_HI + 9728u;
    constexpr uint32_t STAGE   = ST_B_LO + 9728u;

    extern __shared__ char sm[];
    const uint32_t smb = smem_u32(sm);
    const int tid  = threadIdx.x;
    const int lane = tid & 31;
    const int warp = tid >> 5;
    const int wm = warp % NWM;
    const int wn = warp / NWM;
    const int bm = blockIdx.y * BM;
    const int bn = blockIdx.x * 128;

    const uint32_t aLd = (uint32_t)((wm * 32 + (lane & 15)) * 80 +
                                    ((lane >> 4) & 1) * 16);
    const uint32_t bLd = (uint32_t)((lane & 15) * 304 + (lane >> 4) * 16 +
                                    wn * 128);

    float acc[2][8][4];
#pragma unroll
    for (int i = 0; i < 2; i++)
#pragma unroll
        for (int j = 0; j < 8; j++)
#pragma unroll
            for (int q = 0; q < 4; q++) acc[i][j][q] = 0.f;

    const int nc = K >> 5;

    auto issue = [&](int c, int stg) {
        if (c < nc) {
            const uint32_t st = smb + (uint32_t)stg * STAGE;
            const size_t kof = (size_t)c * 32;
#pragma unroll
            for (int i = 0; i < 2; i++) {
                int id = tid + i * NTHR;
                int r = id >> 2, cc = id & 3;
                uint32_t d = st + (uint32_t)(r * 80 + cc * 16);
                size_t so = (size_t)(bm + r) * K + kof + cc * 8;
                CP16(d, Ahi + so);
                CP16(d + ST_A_LO, Alo + so);
            }
#pragma unroll
            for (int i = 0; i < 512 / NTHR; i++) {
                int id = tid + i * NTHR;
                int kr = id >> 4, ncc = id & 15;
                uint32_t d = st + ST_B_HI + (uint32_t)(kr * 304 + ncc * 16);
                size_t so = (size_t)(kof + kr) * N + bn + ncc * 8;
                CP16(d, Whi + so);
                CP16(d + 9728u, Wlo + so);
            }
        }
        CP_COMMIT();
    };

#pragma unroll
    for (int s = 0; s < NSTAGE; s++) issue(s, s);

    int rd = 0;
    for (int c = 0; c < nc; c++) {
        asm volatile("cp.async.wait_group %0;" :: "n"(NSTAGE - 1) : "memory");
        __syncthreads();
        const uint32_t sb = smb + (uint32_t)rd * STAGE;
#pragma unroll
        for (int ks = 0; ks < 2; ks++) {
            uint32_t ah[2][4], al[2][4];
#pragma unroll
            for (int tm = 0; tm < 2; tm++) {
                uint32_t off = aLd + (uint32_t)(tm * 16 * 80 + ks * 32);
                ldsm_x4(ah[tm], sb + off);
                ldsm_x4(al[tm], sb + ST_A_LO + off);
            }
#pragma unroll
            for (int p = 0; p < 4; p++) {
                uint32_t off = bLd + (uint32_t)(ks * 16 * 304 + p * 32);
                uint32_t bh[4], bl[4];
                ldsm_x4t(bh, sb + ST_B_HI + off);
                ldsm_x4t(bl, sb + ST_B_LO + off);
#pragma unroll
                for (int h = 0; h < 2; h++) {
#pragma unroll
                    for (int tm = 0; tm < 2; tm++) {
                        mma_bf16(acc[tm][p * 2 + h], ah[tm], bh + 2 * h);
                        mma_bf16(acc[tm][p * 2 + h], ah[tm], bl + 2 * h);
                        mma_bf16(acc[tm][p * 2 + h], al[tm], bh + 2 * h);
                    }
                }
            }
        }
        __syncthreads();
        issue(c + NSTAGE, rd);
        rd = (rd + 1 == NSTAGE) ? 0 : rd + 1;
    }

    // ---- epilogue ----
#pragma unroll
    for (int tm = 0; tm < 2; tm++) {
#pragma unroll
        for (int bt = 0; bt < 8; bt++) {
            int r0  = bm + wm * 32 + tm * 16 + (lane >> 2);
            int col = bn + wn * 64 + bt * 8 + (lane & 3) * 2;
            float2 v0 = make_float2(acc[tm][bt][0], acc[tm][bt][1]);
            float2 v1 = make_float2(acc[tm][bt][2], acc[tm][bt][3]);
            if (bias) {
                float2 bb = *(const float2*)(bias + col);
                v0.x += bb.x; v0.y += bb.y;
                v1.x += bb.x; v1.y += bb.y;
            }
            if (res) {
                float2 r0v = *(const float2*)(res + (size_t)r0 * N + col);
                float2 r1v = *(const float2*)(res + (size_t)(r0 + 8) * N + col);
                v0.x += r0v.x; v0.y += r0v.y;
                v1.x += r1v.x; v1.y += r1v.y;
            }
            *(float2*)(C + (size_t)r0 * N + col) = v0;
            *(float2*)(C + (size_t)(r0 + 8) * N + col) = v1;
        }
    }
}

// ---------------- embedding gather ----------------
__global__ void embed_kernel(const int* __restrict__ ids,
                             const float* __restrict__ emb,
                             float* __restrict__ h) {
    int i = blockIdx.x * blockDim.x + threadIdx.x;
    int s = i / (HID / 4);
    int c = i % (HID / 4);
    int tok = ids[s];
    float4 v = ((const float4*)(emb + (size_t)tok * HID))[c];
    ((float4*)(h + (size_t)s * HID))[c] = v;
}

// ---------------- RMSNorm -> bf16 hi/lo planes ----------------
__global__ void rmsnorm_split_kernel(const float* __restrict__ x,
                                     const float* __restrict__ w,
                                     __nv_bfloat16* __restrict__ hi,
                                     __nv_bfloat16* __restrict__ lo) {
    int row = blockIdx.x;
    const float4* xr = (const float4*)(x + (size_t)row * HID);
    const float4* wr = (const float4*)w;

    float4 v0 = xr[threadIdx.x];
    float4 v1 = xr[threadIdx.x + 256];
    float ss = v0.x * v0.x + v0.y * v0.y + v0.z * v0.z + v0.w * v0.w
             + v1.x * v1.x + v1.y * v1.y + v1.z * v1.z + v1.w * v1.w;

    __shared__ float red[8];
    for (int o = 16; o > 0; o >>= 1) ss += __shfl_down_sync(0xffffffffu, ss, o);
    if ((threadIdx.x & 31) == 0) red[threadIdx.x >> 5] = ss;
    __syncthreads();
    if (threadIdx.x < 8) {
        float t = red[threadIdx.x];
        for (int o = 4; o > 0; o >>= 1) t += __shfl_down_sync(0xffu, t, o);
        if (threadIdx.x == 0) red[0] = t;
    }
    __syncthreads();
    float inv = rsqrtf(red[0] / (float)HID + 1e-6f);

    float4 w0 = wr[threadIdx.x];
    float4 w1 = wr[threadIdx.x + 256];
    float4 o0, o1;
    o0.x = v0.x * inv * w0.x; o0.y = v0.y * inv * w0.y;
    o0.z = v0.z * inv * w0.z; o0.w = v0.w * inv * w0.w;
    o1.x = v1.x * inv * w1.x; o1.y = v1.y * inv * w1.y;
    o1.z = v1.z * inv * w1.z; o1.w = v1.w * inv * w1.w;
    uint2 h, l;
    size_t b = (size_t)row * (HID / 4);
    split4(o0, h, l);
    ((uint2*)hi)[b + threadIdx.x] = h;
    ((uint2*)lo)[b + threadIdx.x] = l;
    split4(o1, h, l);
    ((uint2*)hi)[b + threadIdx.x + 256] = h;
    ((uint2*)lo)[b + threadIdx.x + 256] = l;
}

// ---------------- RoPE (in place on packed qkv) ----------------
__global__ void rope_kernel(float* __restrict__ qkv) {
    int s = blockIdx.x;
    int hh = blockIdx.y;   // 0..19 : 16 q heads then 4 k heads
    int i = threadIdx.x;
    float inv = powf(1000000.0f, -(float)i / 64.0f);
    float f = (float)s * inv;
    float c = cosf(f), sn = sinf(f);
    float* base = qkv + (size_t)s * NQKV +
                  ((hh < NHEAD) ? hh * HDIM : HID + (hh - NHEAD) * HDIM);
    float x1 = base[i];
    float x2 = base[i + 64];
    base[i]      = x1 * c - x2 * sn;
    base[i + 64] = x2 * c + x1 * sn;
}

// ---------------- flash attention (fp32 SIMT, causal, GQA), split output ----------------
#define LDQ 132
#define ATTN_SMEM ((3 * 64 * LDQ + 64 * 65 + 3 * 64) * 4)

__global__ __launch_bounds__(256) void attn_kernel(
    const float* __restrict__ q, const float* __restrict__ k,
    const float* __restrict__ v,
    __nv_bfloat16* __restrict__ ohi, __nv_bfloat16* __restrict__ olo) {
    extern __shared__ float smf[];
    float* Qs   = smf;
    float* Ks   = Qs + 64 * LDQ;
    float* Vs   = Ks + 64 * LDQ;
    float* Ss   = Vs + 64 * LDQ;
    float* Mrow = Ss + 64 * 65;
    float* Lrow = Mrow + 64;
    float* Arow = Lrow + 64;

    const int head = blockIdx.x;
    const int qb   = blockIdx.y;
    const int kvh  = head >> 2;
    const int tid  = threadIdx.x;

    for (int i = tid; i < 64 * 32; i += 256) {
        int r = i >> 5, c4 = (i & 31) << 2;
        *(float4*)(Qs + r * LDQ + c4) =
            *(const float4*)(q + (size_t)(qb * 64 + r) * NQKV + head * HDIM + c4);
    }
    if (tid < 64) { Mrow[tid] = -1e30f; Lrow[tid] = 0.f; }

    float acc[4][8];
#pragma unroll
    for (int i = 0; i < 4; i++)
#pragma unroll
        for (int j = 0; j < 8; j++) acc[i][j] = 0.f;

    const int i0 = (tid >> 4) * 4;
    const int j0 = (tid & 15) * 4;
    const int d0 = (tid & 15) * 8;
    const float scale = 0.08838834764831845f;

    for (int kb = 0; kb <= qb; kb++) {
        __syncthreads();
        for (int i = tid; i < 64 * 32; i += 256) {
            int r = i >> 5, c4 = (i & 31) << 2;
            size_t off = (size_t)(kb * 64 + r) * NQKV + kvh * HDIM + c4;
            *(float4*)(Ks + r * LDQ + c4) = *(const float4*)(k + off);
            *(float4*)(Vs + r * LDQ + c4) = *(const float4*)(v + off);
        }
        __syncthreads();

        float sc[4][4];
#pragma unroll
        for (int a = 0; a < 4; a++)
#pragma unroll
            for (int b = 0; b < 4; b++) sc[a][b] = 0.f;
        for (int d4 = 0; d4 < HDIM; d4 += 4) {
            float4 qv[4], kv[4];
#pragma unroll
            for (int a = 0; a < 4; a++) qv[a] = *(const float4*)(Qs + (i0 + a) * LDQ + d4);
#pragma unroll
            for (int b = 0; b < 4; b++) kv[b] = *(const float4*)(Ks + (j0 + b) * LDQ + d4);
#pragma unroll
            for (int a = 0; a < 4; a++)
#pragma unroll
                for (int b = 0; b < 4; b++)
                    sc[a][b] += qv[a].x * kv[b].x + qv[a].y * kv[b].y
                              + qv[a].z * kv[b].z + qv[a].w * kv[b].w;
        }
#pragma unroll
        for (int a = 0; a < 4; a++)
#pragma unroll
            for (int b = 0; b < 4; b++) {
                float val = sc[a][b] * scale;
                if (kb == qb && (j0 + b) > (i0 + a)) val = -1e9f;
                Ss[(i0 + a) * 65 + (j0 + b)] = val;
            }
        __syncthreads();

        if (tid < 64) {
            int i = tid;
            float m = Mrow[i];
            float mb = -1e30f;
            for (int j = 0; j < 64; j++) mb = fmaxf(mb, Ss[i * 65 + j]);
            float mn = fmaxf(m, mb);
            float a = expf(m - mn);
            float s = 0.f;
            for (int j = 0; j < 64; j++) {
                float p = expf(Ss[i * 65 + j] - mn);
                Ss[i * 65 + j] = p;
                s += p;
            }
            Lrow[i] = Lrow[i] * a + s;
            Mrow[i] = mn;
            Arow[i] = a;
        }
        __syncthreads();

#pragma unroll
        for (int a = 0; a < 4; a++) {
            float al = Arow[i0 + a];
#pragma unroll
            for (int d = 0; d < 8; d++) acc[a][d] *= al;
        }
        for (int j = 0; j < 64; j++) {
            float4 v0 = *(const float4*)(Vs + j * LDQ + d0);
            float4 v1 = *(const float4*)(Vs + j * LDQ + d0 + 4);
#pragma unroll
            for (int a = 0; a < 4; a++) {
                float p = Ss[(i0 + a) * 65 + j];
                acc[a][0] += p * v0.x; acc[a][1] += p * v0.y;
                acc[a][2] += p * v0.z; acc[a][3] += p * v0.w;
                acc[a][4] += p * v1.x; acc[a][5] += p * v1.y;
                acc[a][6] += p * v1.z; acc[a][7] += p * v1.w;
            }
        }
    }

#pragma unroll
    for (int a = 0; a < 4; a++) {
        float linv = 1.0f / Lrow[i0 + a];
        int row = qb * 64 + i0 + a;
        float4 o0, o1;
        o0.x = acc[a][0] * linv; o0.y = acc[a][1] * linv;
        o0.z = acc[a][2] * linv; o0.w = acc[a][3] * linv;
        o1.x = acc[a][4] * linv; o1.y = acc[a][5] * linv;
        o1.z = acc[a][6] * linv; o1.w = acc[a][7] * linv;
        size_t b4 = ((size_t)row * HID + head * HDIM + d0) >> 2;
        uint2 h, l;
        split4(o0, h, l);
        ((uint2*)ohi)[b4] = h;
        ((uint2*)olo)[b4] = l;
        split4(o1, h, l);
        ((uint2*)ohi)[b4 + 1] = h;
        ((uint2*)olo)[b4 + 1] = l;
    }
}

// ---------------- SiLU(g) * u -> bf16 hi/lo planes ----------------
__global__ void silu_split_kernel(const float* __restrict__ g,
                                  const float* __restrict__ u,
                                  __nv_bfloat16* __restrict__ hi,
                                  __nv_bfloat16* __restrict__ lo) {
    int i = blockIdx.x * blockDim.x + threadIdx.x;
    float4 gv = ((const float4*)g)[i];
    float4 uv = ((const float4*)u)[i];
    gv.x = gv.x / (1.f + expf(-gv.x)) * uv.x;
    gv.y = gv.y / (1.f + expf(-gv.y)) * uv.y;
    gv.z = gv.z / (1.f + expf(-gv.z)) * uv.z;
    gv.w = gv.w / (1.f + expf(-gv.w)) * uv.w;
    uint2 h, l;
    split4(gv, h, l);
    ((uint2*)hi)[i] = h;
    ((uint2*)lo)[i] = l;
}

// ---------------- host orchestration ----------------
static __nv_bfloat16 *s_ahi, *s_alo, *s_whi, *s_wlo;

static void run_split(const float* src, size_t n) {
    int n4 = (int)(n / 4);
    split_kernel<<<(n4 + 255) / 256, 256>>>(src, s_whi, s_wlo, n4);
}
static void run_gemm(const float* bias, const float* res, float* C,
                     int M, int N, int K) {
    if (N >= 8192) {
        dim3 grid(N / 128, M / 256);
        gemm_ps_kernel<256, 3><<<grid, 512, 181248>>>(
            s_ahi, s_alo, s_whi, s_wlo, bias, res, C, M, N, K);
    } else {
        dim3 grid(N / 128, M / 128);
        gemm_ps_kernel<128, 2><<<grid, 256, 79872>>>(
            s_ahi, s_alo, s_whi, s_wlo, bias, res, C, M, N, K);
    }
}

extern "C" void kernel_launch(void* const* d_in, const int* in_sizes, int n_in,
                              void* d_out, int out_size) {
    const int*   ids    = (const int*)d_in[0];
    const float* emb    = (const float*)d_in[1];
    const float* Wq     = (const float*)d_in[2];
    const float* bq     = (const float*)d_in[3];
    const float* Wk     = (const float*)d_in[4];
    const float* bk     = (const float*)d_in[5];
    const float* Wv     = (const float*)d_in[6];
    const float* bv     = (const float*)d_in[7];
    const float* Wo     = (const float*)d_in[8];
    const float* ln1    = (const float*)d_in[9];
    const float* ln2    = (const float*)d_in[10];
    const float* Wg     = (const float*)d_in[11];
    const float* Wu     = (const float*)d_in[12];
    const float* Wd     = (const float*)d_in[13];
    const float* norm_w = (const float*)d_in[14];
    const float* Wlm    = (const float*)d_in[15];
    const float* blm    = (const float*)d_in[16];
    float* out = (float*)d_out;

    float* base = nullptr;
    cudaGetSymbolAddress((void**)&base, g_scratch);
    cudaGetSymbolAddress((void**)&s_ahi, g_ahi);
    cudaGetSymbolAddress((void**)&s_alo, g_alo);
    cudaGetSymbolAddress((void**)&s_whi, g_whi);
    cudaGetSymbolAddress((void**)&s_wlo, g_wlo);

    float* hbuf  = base;
    float* qkv   = base + (size_t)SH;
    float* gbuf  = qkv + (size_t)SQ * NQKV;
    float* ubuf  = gbuf + (size_t)SFF;
    float* bpack = ubuf + (size_t)SFF;

    cudaFuncSetAttribute(attn_kernel, cudaFuncAttributeMaxDynamicSharedMemorySize,
                         ATTN_SMEM);
    cudaFuncSetAttribute(gemm_ps_kernel<128, 2>,
                         cudaFuncAttributeMaxDynamicSharedMemorySize, 79872);
    cudaFuncSetAttribute(gemm_ps_kernel<256, 3>,
                         cudaFuncAttributeMaxDynamicSharedMemorySize, 181248);

    embed_kernel<<<SH / 4 / 256, 256>>>(ids, emb, hbuf);

    for (int l = 0; l < NLAYER; l++) {
        const float* Wql = Wq + (size_t)l * HID * HID;
        const float* bql = bq + (size_t)l * HID;
        const float* Wkl = Wk + (size_t)l * HID * (NKVH * HDIM);
        const float* bkl = bk + (size_t)l * (NKVH * HDIM);
        const float* Wvl = Wv + (size_t)l * HID * (NKVH * HDIM);
        const float* bvl = bv + (size_t)l * (NKVH * HDIM);
        const float* Wol = Wo + (size_t)l * HID * HID;
        const float* l1  = ln1 + (size_t)l * HID;
        const float* l2  = ln2 + (size_t)l * HID;
        const float* Wgl = Wg + (size_t)l * HID * FFD;
        const float* Wul = Wu + (size_t)l * HID * FFD;
        const float* Wdl = Wd + (size_t)l * FFD * HID;

        // fused QKV projection (launch order keeps the GEMM at profile slot 6)
        biaspack_kernel<<<NQKV / 256, 256>>>(bql, bkl, bvl, bpack);
        rmsnorm_split_kernel<<<SQ, 256>>>(hbuf, l1, s_ahi, s_alo);
        {   // Wq -> qkv cols [0,2048)
            int total4 = (int)((size_t)HID * HID / 4);
            split2d_kernel<<<(total4 + 255) / 256, 256>>>(
                Wql, s_whi, s_wlo, HID / 4, NQKV / 4, total4);
        }
        splitkv_kernel<<<HID * 1024 / 4 / 256, 256>>>(Wkl, Wvl, s_whi, s_wlo);
        run_gemm(bpack, nullptr, qkv, SQ, NQKV, HID);

        dim3 rgrid(SQ, NHEAD + NKVH);
        rope_kernel<<<rgrid, 64>>>(qkv);

        dim3 agrid(NHEAD, SQ / 64);
        attn_kernel<<<agrid, 256, ATTN_SMEM>>>(qkv, qkv + HID,
                                               qkv + HID + NKVH * HDIM,
                                               s_ahi, s_alo);

        run_split(Wol, (size_t)HID * HID);
        run_gemm(nullptr, hbuf, hbuf, SQ, HID, HID);

        rmsnorm_split_kernel<<<SQ, 256>>>(hbuf, l2, s_ahi, s_alo);
        run_split(Wgl, (size_t)HID * FFD);
        run_gemm(nullptr, nullptr, gbuf, SQ, FFD, HID);
        run_split(Wul, (size_t)HID * FFD);
        run_gemm(nullptr, nullptr, ubuf, SQ, FFD, HID);
        silu_split_kernel<<<SFF / 4 / 256, 256>>>(gbuf, ubuf, s_ahi, s_alo);
        run_split(Wdl, (size_t)FFD * HID);
        run_gemm(nullptr, hbuf, hbuf, SQ, HID, FFD);
    }

    rmsnorm_split_kernel<<<SQ, 256>>>(hbuf, norm_w, s_ahi, s_alo);
    run_split(Wlm, (size_t)HID * VOC);
    run_gemm(blm, nullptr, out, SQ, VOC, HID);
}

// round 8
// speedup vs baseline: 1.1452x; 1.0412x over previous
#include <cuda_runtime.h>
#include <cuda_bf16.h>
#include <math.h>
#include <cstdint>

// ---------------- problem constants ----------------
#define SQ     2048
#define HID    2048
#define VOC    32000
#define NHEAD  16
#define NKVH   4
#define HDIM   128
#define FFD    8192
#define NLAYER 4
#define NQKV   3072   // 2048 + 512 + 512

#define SH  (SQ * HID)
#define SFF (SQ * FFD)

// hbuf SH + qkv SQ*NQKV + gbuf SFF + ubuf SFF + bpack 4096
__device__ float g_scratch[(size_t)SH + (size_t)SQ * NQKV + 2 * (size_t)SFF + 4096];
__device__ __nv_bfloat16 g_ahi[(size_t)SFF];
__device__ __nv_bfloat16 g_alo[(size_t)SFF];
__device__ __nv_bfloat16 g_whi[(size_t)HID * VOC];
__device__ __nv_bfloat16 g_wlo[(size_t)HID * VOC];

// ======================= helpers =======================
__device__ __forceinline__ uint32_t smem_u32(const void* p) {
    uint32_t a;
    asm("{ .reg .u64 t; cvta.to.shared.u64 t, %1; cvt.u32.u64 %0, t; }"
        : "=r"(a) : "l"(p));
    return a;
}
__device__ __forceinline__ void ldsm_x4(uint32_t* r, uint32_t addr) {
    asm volatile("ldmatrix.sync.aligned.m8n8.x4.shared.b16 {%0,%1,%2,%3}, [%4];"
                 : "=r"(r[0]), "=r"(r[1]), "=r"(r[2]), "=r"(r[3]) : "r"(addr));
}
__device__ __forceinline__ void ldsm_x4t(uint32_t* r, uint32_t addr) {
    asm volatile("ldmatrix.sync.aligned.m8n8.x4.trans.shared.b16 {%0,%1,%2,%3}, [%4];"
                 : "=r"(r[0]), "=r"(r[1]), "=r"(r[2]), "=r"(r[3]) : "r"(addr));
}
__device__ __forceinline__ void mma_bf16(float* c, const uint32_t* a,
                                         const uint32_t* b) {
    asm volatile("mma.sync.aligned.m16n8k16.row.col.f32.bf16.bf16.f32 "
                 "{%0,%1,%2,%3}, {%4,%5,%6,%7}, {%8,%9}, {%0,%1,%2,%3};"
                 : "+f"(c[0]), "+f"(c[1]), "+f"(c[2]), "+f"(c[3])
                 : "r"(a[0]), "r"(a[1]), "r"(a[2]), "r"(a[3]),
                   "r"(b[0]), "r"(b[1]));
}
__device__ __forceinline__ uint32_t pack2(__nv_bfloat16 a, __nv_bfloat16 b) {
    uint16_t ua = *(uint16_t*)&a, ub = *(uint16_t*)&b;
    return ((uint32_t)ub << 16) | (uint32_t)ua;
}
__device__ __forceinline__ void split4(float4 f, uint2& hi, uint2& lo) {
    __nv_bfloat16 hx = __float2bfloat16_rn(f.x);
    __nv_bfloat16 hy = __float2bfloat16_rn(f.y);
    __nv_bfloat16 hz = __float2bfloat16_rn(f.z);
    __nv_bfloat16 hw = __float2bfloat16_rn(f.w);
    __nv_bfloat16 lx = __float2bfloat16_rn(f.x - __bfloat162float(hx));
    __nv_bfloat16 ly = __float2bfloat16_rn(f.y - __bfloat162float(hy));
    __nv_bfloat16 lz = __float2bfloat16_rn(f.z - __bfloat162float(hz));
    __nv_bfloat16 lw = __float2bfloat16_rn(f.w - __bfloat162float(hw));
    hi = make_uint2(pack2(hx, hy), pack2(hz, hw));
    lo = make_uint2(pack2(lx, ly), pack2(lz, lw));
}
#define CP16(dst, src) \
    asm volatile("cp.async.cg.shared.global [%0], [%1], 16;" :: "r"(dst), "l"(src))
#define CP_COMMIT() asm volatile("cp.async.commit_group;" ::: "memory")

// ---------------- weight splits (MLP=4) ----------------
__global__ void split_kernel(const float* __restrict__ src,
                             __nv_bfloat16* __restrict__ hi,
                             __nv_bfloat16* __restrict__ lo, int nT) {
    int i = blockIdx.x * blockDim.x + threadIdx.x;   // nT threads, 4 each
    float4 f[4];
#pragma unroll
    for (int j = 0; j < 4; j++) f[j] = ((const float4*)src)[i + j * nT];
#pragma unroll
    for (int j = 0; j < 4; j++) {
        uint2 h, l;
        split4(f[j], h, l);
        ((uint2*)hi)[i + j * nT] = h;
        ((uint2*)lo)[i + j * nT] = l;
    }
}
// src is [K, n] contiguous; planes row stride ld4*4 (uint2 units); offset prebaked.
__global__ void split2d_kernel(const float* __restrict__ src,
                               __nv_bfloat16* __restrict__ hi,
                               __nv_bfloat16* __restrict__ lo,
                               int n4row, int ld4, int nT) {
    int i = blockIdx.x * blockDim.x + threadIdx.x;
    float4 f[4];
#pragma unroll
    for (int j = 0; j < 4; j++) f[j] = ((const float4*)src)[i + j * nT];
#pragma unroll
    for (int j = 0; j < 4; j++) {
        int idx = i + j * nT;
        int r = idx / n4row, c = idx % n4row;
        uint2 h, l;
        split4(f[j], h, l);
        ((uint2*)hi)[(size_t)r * ld4 + c] = h;
        ((uint2*)lo)[(size_t)r * ld4 + c] = l;
    }
}
// merged K+V split into qkv weight planes at column offset HID (MLP=4)
__global__ void splitkv_kernel(const float* __restrict__ Wk,
                               const float* __restrict__ Wv,
                               __nv_bfloat16* __restrict__ hi,
                               __nv_bfloat16* __restrict__ lo, int nT) {
    int i = blockIdx.x * blockDim.x + threadIdx.x;
#pragma unroll
    for (int j = 0; j < 4; j++) {
        int idx = i + j * nT;          // over HID*1024/4
        int r = idx >> 8;
        int c4 = idx & 255;
        const float* src = (c4 < 128) ? Wk + (size_t)r * 512 + c4 * 4
                                      : Wv + (size_t)r * 512 + (c4 - 128) * 4;
        uint2 h, l;
        split4(*(const float4*)src, h, l);
        size_t o = (size_t)r * (NQKV / 4) + (HID / 4) + c4;
        ((uint2*)hi)[o] = h;
        ((uint2*)lo)[o] = l;
    }
}
// pack bq|bk|bv -> bpack[3072]
__global__ void biaspack_kernel(const float* __restrict__ bq,
                                const float* __restrict__ bk,
                                const float* __restrict__ bv,
                                float* __restrict__ bp) {
    int i = blockIdx.x * blockDim.x + threadIdx.x;
    if (i >= NQKV) return;
    bp[i] = (i < HID) ? bq[i]
          : (i < HID + 512) ? bk[i - HID] : bv[i - HID - 512];
}

// ======================= BM=128 GEMM (R5/R7-proven, unchanged) =======================
template<int BM, int NSTAGE>
__global__ __launch_bounds__(BM * 2, (BM == 128) ? 2 : 1)
void gemm_ps_kernel(const __nv_bfloat16* __restrict__ Ahi,
                    const __nv_bfloat16* __restrict__ Alo,
                    const __nv_bfloat16* __restrict__ Whi,
                    const __nv_bfloat16* __restrict__ Wlo,
                    const float* __restrict__ bias, const float* __restrict__ res,
                    float* __restrict__ C, int M, int N, int K) {
    constexpr int NTHR = BM * 2;
    constexpr int NWM  = BM / 32;
    constexpr uint32_t ST_A_LO = (uint32_t)BM * 80u;
    constexpr uint32_t ST_B_HI = 2u * BM * 80u;
    constexpr uint32_t ST_B_LO = ST_B_HI + 9728u;
    constexpr uint32_t STAGE   = ST_B_LO + 9728u;

    extern __shared__ char sm[];
    const uint32_t smb = smem_u32(sm);
    const int tid  = threadIdx.x;
    const int lane = tid & 31;
    const int warp = tid >> 5;
    const int wm = warp % NWM;
    const int wn = warp / NWM;
    const int bm = blockIdx.y * BM;
    const int bn = blockIdx.x * 128;

    const uint32_t aLd = (uint32_t)((wm * 32 + (lane & 15)) * 80 +
                                    ((lane >> 4) & 1) * 16);
    const uint32_t bLd = (uint32_t)((lane & 15) * 304 + (lane >> 4) * 16 +
                                    wn * 128);

    float acc[2][8][4];
#pragma unroll
    for (int i = 0; i < 2; i++)
#pragma unroll
        for (int j = 0; j < 8; j++)
#pragma unroll
            for (int q = 0; q < 4; q++) acc[i][j][q] = 0.f;

    const int nc = K >> 5;

    auto issue = [&](int c, int stg) {
        if (c < nc) {
            const uint32_t st = smb + (uint32_t)stg * STAGE;
            const size_t kof = (size_t)c * 32;
#pragma unroll
            for (int i = 0; i < 2; i++) {
                int id = tid + i * NTHR;
                int r = id >> 2, cc = id & 3;
                uint32_t d = st + (uint32_t)(r * 80 + cc * 16);
                size_t so = (size_t)(bm + r) * K + kof + cc * 8;
                CP16(d, Ahi + so);
                CP16(d + ST_A_LO, Alo + so);
            }
#pragma unroll
            for (int i = 0; i < 512 / NTHR; i++) {
                int id = tid + i * NTHR;
                int kr = id >> 4, ncc = id & 15;
                uint32_t d = st + ST_B_HI + (uint32_t)(kr * 304 + ncc * 16);
                size_t so = (size_t)(kof + kr) * N + bn + ncc * 8;
                CP16(d, Whi + so);
                CP16(d + 9728u, Wlo + so);
            }
        }
        CP_COMMIT();
    };

#pragma unroll
    for (int s = 0; s < NSTAGE; s++) issue(s, s);

    int rd = 0;
    for (int c = 0; c < nc; c++) {
        asm volatile("cp.async.wait_group %0;" :: "n"(NSTAGE - 1) : "memory");
        __syncthreads();
        const uint32_t sb = smb + (uint32_t)rd * STAGE;
#pragma unroll
        for (int ks = 0; ks < 2; ks++) {
            uint32_t ah[2][4], al[2][4];
#pragma unroll
            for (int tm = 0; tm < 2; tm++) {
                uint32_t off = aLd + (uint32_t)(tm * 16 * 80 + ks * 32);
                ldsm_x4(ah[tm], sb + off);
                ldsm_x4(al[tm], sb + ST_A_LO + off);
            }
#pragma unroll
            for (int p = 0; p < 4; p++) {
                uint32_t off = bLd + (uint32_t)(ks * 16 * 304 + p * 32);
                uint32_t bh[4], bl[4];
                ldsm_x4t(bh, sb + ST_B_HI + off);
                ldsm_x4t(bl, sb + ST_B_LO + off);
#pragma unroll
                for (int h = 0; h < 2; h++) {
#pragma unroll
                    for (int tm = 0; tm < 2; tm++) {
                        mma_bf16(acc[tm][p * 2 + h], ah[tm], bh + 2 * h);
                        mma_bf16(acc[tm][p * 2 + h], ah[tm], bl + 2 * h);
                        mma_bf16(acc[tm][p * 2 + h], al[tm], bh + 2 * h);
                    }
                }
            }
        }
        __syncthreads();
        issue(c + NSTAGE, rd);
        rd = (rd + 1 == NSTAGE) ? 0 : rd + 1;
    }

#pragma unroll
    for (int tm = 0; tm < 2; tm++) {
#pragma unroll
        for (int bt = 0; bt < 8; bt++) {
            int r0  = bm + wm * 32 + tm * 16 + (lane >> 2);
            int col = bn + wn * 64 + bt * 8 + (lane & 3) * 2;
            float2 v0 = make_float2(acc[tm][bt][0], acc[tm][bt][1]);
            float2 v1 = make_float2(acc[tm][bt][2], acc[tm][bt][3]);
            if (bias) {
                float2 bb = *(const float2*)(bias + col);
                v0.x += bb.x; v0.y += bb.y;
                v1.x += bb.x; v1.y += bb.y;
            }
            if (res) {
                float2 r0v = *(const float2*)(res + (size_t)r0 * N + col);
                float2 r1v = *(const float2*)(res + (size_t)(r0 + 8) * N + col);
                v0.x += r0v.x; v0.y += r0v.y;
                v1.x += r1v.x; v1.y += r1v.y;
            }
            *(float2*)(C + (size_t)r0 * N + col) = v0;
            *(float2*)(C + (size_t)(r0 + 8) * N + col) = v1;
        }
    }
}

// ======================= BM=256 big GEMM: single-sync multistage + B prefetch =======================
// BM=256, BN=128, BK=32, 512 thr, 3 stages.
#define BST_A_LO 20480u
#define BST_B_HI 40960u
#define BST_B_LO 50688u
#define BSTAGE   60416u
#define BIG_SMEM (3 * 60416)

__global__ __launch_bounds__(512, 1)
void gemm_big_kernel(const __nv_bfloat16* __restrict__ Ahi,
                     const __nv_bfloat16* __restrict__ Alo,
                     const __nv_bfloat16* __restrict__ Whi,
                     const __nv_bfloat16* __restrict__ Wlo,
                     const float* __restrict__ bias, const float* __restrict__ res,
                     float* __restrict__ C, int M, int N, int K) {
    extern __shared__ char sm[];
    const uint32_t smb = smem_u32(sm);
    const int tid  = threadIdx.x;
    const int lane = tid & 31;
    const int warp = tid >> 5;
    const int wm = warp & 7;
    const int wn = warp >> 3;
    const int bm = blockIdx.y * 256;
    const int bn = blockIdx.x * 128;

    const uint32_t aLd = (uint32_t)((wm * 32 + (lane & 15)) * 80 +
                                    ((lane >> 4) & 1) * 16);
    const uint32_t bLd = (uint32_t)((lane & 15) * 304 + (lane >> 4) * 16 +
                                    wn * 128);

    float acc[2][8][4];
#pragma unroll
    for (int i = 0; i < 2; i++)
#pragma unroll
        for (int j = 0; j < 8; j++)
#pragma unroll
            for (int q = 0; q < 4; q++) acc[i][j][q] = 0.f;

    const int nc = K >> 5;

    auto issue = [&](int c, int stg) {
        if (c < nc) {
            const uint32_t st = smb + (uint32_t)stg * BSTAGE;
            const size_t kof = (size_t)c * 32;
#pragma unroll
            for (int i = 0; i < 2; i++) {
                int id = tid + i * 512;
                int r = id >> 2, cc = id & 3;
                uint32_t d = st + (uint32_t)(r * 80 + cc * 16);
                size_t so = (size_t)(bm + r) * K + kof + cc * 8;
                CP16(d, Ahi + so);
                CP16(d + BST_A_LO, Alo + so);
            }
            {
                int kr = tid >> 4, ncc = tid & 15;
                uint32_t d = st + BST_B_HI + (uint32_t)(kr * 304 + ncc * 16);
                size_t so = (size_t)(kof + kr) * N + bn + ncc * 8;
                CP16(d, Whi + so);
                CP16(d + 9728u, Wlo + so);
            }
        }
        CP_COMMIT();
    };

    issue(0, 0);
    issue(1, 1);

    for (int c = 0; c < nc; c++) {
        asm volatile("cp.async.wait_group 1;" ::: "memory");
        __syncthreads();
        issue(c + 2, (c + 2) % 3);             // overlaps with compute below
        const uint32_t sb = smb + (uint32_t)(c % 3) * BSTAGE;
#pragma unroll
        for (int ks = 0; ks < 2; ks++) {
            uint32_t ah[2][4], al[2][4];
#pragma unroll
            for (int tm = 0; tm < 2; tm++) {
                uint32_t off = aLd + (uint32_t)(tm * 16 * 80 + ks * 32);
                ldsm_x4(ah[tm], sb + off);
                ldsm_x4(al[tm], sb + BST_A_LO + off);
            }
            uint32_t bh[2][4], bl[2][4];
            {
                uint32_t off = bLd + (uint32_t)(ks * 16 * 304);
                ldsm_x4t(bh[0], sb + BST_B_HI + off);
                ldsm_x4t(bl[0], sb + BST_B_LO + off);
            }
#pragma unroll
            for (int p = 0; p < 4; p++) {
                const int cur = p & 1, nxt = cur ^ 1;
                if (p < 3) {
                    uint32_t off = bLd + (uint32_t)(ks * 16 * 304 + (p + 1) * 32);
                    ldsm_x4t(bh[nxt], sb + BST_B_HI + off);
                    ldsm_x4t(bl[nxt], sb + BST_B_LO + off);
                }
#pragma unroll
                for (int h = 0; h < 2; h++) {
#pragma unroll
                    for (int tm = 0; tm < 2; tm++) {
                        mma_bf16(acc[tm][p * 2 + h], ah[tm], bh[cur] + 2 * h);
                        mma_bf16(acc[tm][p * 2 + h], ah[tm], bl[cur] + 2 * h);
                        mma_bf16(acc[tm][p * 2 + h], al[tm], bh[cur] + 2 * h);
                    }
                }
            }
        }
    }

#pragma unroll
    for (int tm = 0; tm < 2; tm++) {
#pragma unroll
        for (int bt = 0; bt < 8; bt++) {
            int r0  = bm + wm * 32 + tm * 16 + (lane >> 2);
            int col = bn + wn * 64 + bt * 8 + (lane & 3) * 2;
            float2 v0 = make_float2(acc[tm][bt][0], acc[tm][bt][1]);
            float2 v1 = make_float2(acc[tm][bt][2], acc[tm][bt][3]);
            if (bias) {
                float2 bb = *(const float2*)(bias + col);
                v0.x += bb.x; v0.y += bb.y;
                v1.x += bb.x; v1.y += bb.y;
            }
            if (res) {
                float2 r0v = *(const float2*)(res + (size_t)r0 * N + col);
                float2 r1v = *(const float2*)(res + (size_t)(r0 + 8) * N + col);
                v0.x += r0v.x; v0.y += r0v.y;
                v1.x += r1v.x; v1.y += r1v.y;
            }
            *(float2*)(C + (size_t)r0 * N + col) = v0;
            *(float2*)(C + (size_t)(r0 + 8) * N + col) = v1;
        }
    }
}

// ---------------- embedding gather ----------------
__global__ void embed_kernel(const int* __restrict__ ids,
                             const float* __restrict__ emb,
                             float* __restrict__ h) {
    int i = blockIdx.x * blockDim.x + threadIdx.x;
    int s = i / (HID / 4);
    int c = i % (HID / 4);
    int tok = ids[s];
    float4 v = ((const float4*)(emb + (size_t)tok * HID))[c];
    ((float4*)(h + (size_t)s * HID))[c] = v;
}

// ---------------- RMSNorm -> bf16 hi/lo planes ----------------
__global__ void rmsnorm_split_kernel(const float* __restrict__ x,
                                     const float* __restrict__ w,
                                     __nv_bfloat16* __restrict__ hi,
                                     __nv_bfloat16* __restrict__ lo) {
    int row = blockIdx.x;
    const float4* xr = (const float4*)(x + (size_t)row * HID);
    const float4* wr = (const float4*)w;

    float4 v0 = xr[threadIdx.x];
    float4 v1 = xr[threadIdx.x + 256];
    float ss = v0.x * v0.x + v0.y * v0.y + v0.z * v0.z + v0.w * v0.w
             + v1.x * v1.x + v1.y * v1.y + v1.z * v1.z + v1.w * v1.w;

    __shared__ float red[8];
    for (int o = 16; o > 0; o >>= 1) ss += __shfl_down_sync(0xffffffffu, ss, o);
    if ((threadIdx.x & 31) == 0) red[threadIdx.x >> 5] = ss;
    __syncthreads();
    if (threadIdx.x < 8) {
        float t = red[threadIdx.x];
        for (int o = 4; o > 0; o >>= 1) t += __shfl_down_sync(0xffu, t, o);
        if (threadIdx.x == 0) red[0] = t;
    }
    __syncthreads();
    float inv = rsqrtf(red[0] / (float)HID + 1e-6f);

    float4 w0 = wr[threadIdx.x];
    float4 w1 = wr[threadIdx.x + 256];
    float4 o0, o1;
    o0.x = v0.x * inv * w0.x; o0.y = v0.y * inv * w0.y;
    o0.z = v0.z * inv * w0.z; o0.w = v0.w * inv * w0.w;
    o1.x = v1.x * inv * w1.x; o1.y = v1.y * inv * w1.y;
    o1.z = v1.z * inv * w1.z; o1.w = v1.w * inv * w1.w;
    uint2 h, l;
    size_t b = (size_t)row * (HID / 4);
    split4(o0, h, l);
    ((uint2*)hi)[b + threadIdx.x] = h;
    ((uint2*)lo)[b + threadIdx.x] = l;
    split4(o1, h, l);
    ((uint2*)hi)[b + threadIdx.x + 256] = h;
    ((uint2*)lo)[b + threadIdx.x + 256] = l;
}

// ---------------- RoPE (in place on packed qkv) ----------------
__global__ void rope_kernel(float* __restrict__ qkv) {
    int s = blockIdx.x;
    int hh = blockIdx.y;
    int i = threadIdx.x;
    float inv = powf(1000000.0f, -(float)i / 64.0f);
    float f = (float)s * inv;
    float c = cosf(f), sn = sinf(f);
    float* base = qkv + (size_t)s * NQKV +
                  ((hh < NHEAD) ? hh * HDIM : HID + (hh - NHEAD) * HDIM);
    float x1 = base[i];
    float x2 = base[i + 64];
    base[i]      = x1 * c - x2 * sn;
    base[i + 64] = x2 * c + x1 * sn;
}

// ---------------- flash attention (fp32 SIMT, causal, GQA), split output ----------------
#define LDQ 132
#define ATTN_SMEM ((3 * 64 * LDQ + 64 * 65 + 3 * 64) * 4)

__global__ __launch_bounds__(256) void attn_kernel(
    const float* __restrict__ q, const float* __restrict__ k,
    const float* __restrict__ v,
    __nv_bfloat16* __restrict__ ohi, __nv_bfloat16* __restrict__ olo) {
    extern __shared__ float smf[];
    float* Qs   = smf;
    float* Ks   = Qs + 64 * LDQ;
    float* Vs   = Ks + 64 * LDQ;
    float* Ss   = Vs + 64 * LDQ;
    float* Mrow = Ss + 64 * 65;
    float* Lrow = Mrow + 64;
    float* Arow = Lrow + 64;

    const int head = blockIdx.x;
    const int qb   = blockIdx.y;
    const int kvh  = head >> 2;
    const int tid  = threadIdx.x;

    for (int i = tid; i < 64 * 32; i += 256) {
        int r = i >> 5, c4 = (i & 31) << 2;
        *(float4*)(Qs + r * LDQ + c4) =
            *(const float4*)(q + (size_t)(qb * 64 + r) * NQKV + head * HDIM + c4);
    }
    if (tid < 64) { Mrow[tid] = -1e30f; Lrow[tid] = 0.f; }

    float acc[4][8];
#pragma unroll
    for (int i = 0; i < 4; i++)
#pragma unroll
        for (int j = 0; j < 8; j++) acc[i][j] = 0.f;

    const int i0 = (tid >> 4) * 4;
    const int j0 = (tid & 15) * 4;
    const int d0 = (tid & 15) * 8;
    const float scale = 0.08838834764831845f;

    for (int kb = 0; kb <= qb; kb++) {
        __syncthreads();
        for (int i = tid; i < 64 * 32; i += 256) {
            int r = i >> 5, c4 = (i & 31) << 2;
            size_t off = (size_t)(kb * 64 + r) * NQKV + kvh * HDIM + c4;
            *(float4*)(Ks + r * LDQ + c4) = *(const float4*)(k + off);
            *(float4*)(Vs + r * LDQ + c4) = *(const float4*)(v + off);
        }
        __syncthreads();

        float sc[4][4];
#pragma unroll
        for (int a = 0; a < 4; a++)
#pragma unroll
            for (int b = 0; b < 4; b++) sc[a][b] = 0.f;
        for (int d4 = 0; d4 < HDIM; d4 += 4) {
            float4 qv[4], kv[4];
#pragma unroll
            for (int a = 0; a < 4; a++) qv[a] = *(const float4*)(Qs + (i0 + a) * LDQ + d4);
#pragma unroll
            for (int b = 0; b < 4; b++) kv[b] = *(const float4*)(Ks + (j0 + b) * LDQ + d4);
#pragma unroll
            for (int a = 0; a < 4; a++)
#pragma unroll
                for (int b = 0; b < 4; b++)
                    sc[a][b] += qv[a].x * kv[b].x + qv[a].y * kv[b].y
                              + qv[a].z * kv[b].z + qv[a].w * kv[b].w;
        }
#pragma unroll
        for (int a = 0; a < 4; a++)
#pragma unroll
            for (int b = 0; b < 4; b++) {
                float val = sc[a][b] * scale;
                if (kb == qb && (j0 + b) > (i0 + a)) val = -1e9f;
                Ss[(i0 + a) * 65 + (j0 + b)] = val;
            }
        __syncthreads();

        if (tid < 64) {
            int i = tid;
            float m = Mrow[i];
            float mb = -1e30f;
            for (int j = 0; j < 64; j++) mb = fmaxf(mb, Ss[i * 65 + j]);
            float mn = fmaxf(m, mb);
            float a = expf(m - mn);
            float s = 0.f;
            for (int j = 0; j < 64; j++) {
                float p = expf(Ss[i * 65 + j] - mn);
                Ss[i * 65 + j] = p;
                s += p;
            }
            Lrow[i] = Lrow[i] * a + s;
            Mrow[i] = mn;
            Arow[i] = a;
        }
        __syncthreads();

#pragma unroll
        for (int a = 0; a < 4; a++) {
            float al = Arow[i0 + a];
#pragma unroll
            for (int d = 0; d < 8; d++) acc[a][d] *= al;
        }
        for (int j = 0; j < 64; j++) {
            float4 v0 = *(const float4*)(Vs + j * LDQ + d0);
            float4 v1 = *(const float4*)(Vs + j * LDQ + d0 + 4);
#pragma unroll
            for (int a = 0; a < 4; a++) {
                float p = Ss[(i0 + a) * 65 + j];
                acc[a][0] += p * v0.x; acc[a][1] += p * v0.y;
                acc[a][2] += p * v0.z; acc[a][3] += p * v0.w;
                acc[a][4] += p * v1.x; acc[a][5] += p * v1.y;
                acc[a][6] += p * v1.z; acc[a][7] += p * v1.w;
            }
        }
    }

#pragma unroll
    for (int a = 0; a < 4; a++) {
        float linv = 1.0f / Lrow[i0 + a];
        int row = qb * 64 + i0 + a;
        float4 o0, o1;
        o0.x = acc[a][0] * linv; o0.y = acc[a][1] * linv;
        o0.z = acc[a][2] * linv; o0.w = acc[a][3] * linv;
        o1.x = acc[a][4] * linv; o1.y = acc[a][5] * linv;
        o1.z = acc[a][6] * linv; o1.w = acc[a][7] * linv;
        size_t b4 = ((size_t)row * HID + head * HDIM + d0) >> 2;
        uint2 h, l;
        split4(o0, h, l);
        ((uint2*)ohi)[b4] = h;
        ((uint2*)olo)[b4] = l;
        split4(o1, h, l);
        ((uint2*)ohi)[b4 + 1] = h;
        ((uint2*)olo)[b4 + 1] = l;
    }
}

// ---------------- SiLU(g) * u -> bf16 hi/lo planes ----------------
__global__ void silu_split_kernel(const float* __restrict__ g,
                                  const float* __restrict__ u,
                                  __nv_bfloat16* __restrict__ hi,
                                  __nv_bfloat16* __restrict__ lo) {
    int i = blockIdx.x * blockDim.x + threadIdx.x;
    float4 gv = ((const float4*)g)[i];
    float4 uv = ((const float4*)u)[i];
    gv.x = gv.x / (1.f + expf(-gv.x)) * uv.x;
    gv.y = gv.y / (1.f + expf(-gv.y)) * uv.y;
    gv.z = gv.z / (1.f + expf(-gv.z)) * uv.z;
    gv.w = gv.w / (1.f + expf(-gv.w)) * uv.w;
    uint2 h, l;
    split4(gv, h, l);
    ((uint2*)hi)[i] = h;
    ((uint2*)lo)[i] = l;
}

// ---------------- host orchestration ----------------
static __nv_bfloat16 *s_ahi, *s_alo, *s_whi, *s_wlo;

static void run_split(const float* src, size_t n) {
    int nT = (int)(n / 16);   // 4 float4 per thread
    split_kernel<<<nT / 256, 256>>>(src, s_whi, s_wlo, nT);
}
static void run_gemm(const float* bias, const float* res, float* C,
                     int M, int N, int K) {
    if (N >= 8192) {
        dim3 grid(N / 128, M / 256);
        gemm_big_kernel<<<grid, 512, BIG_SMEM>>>(
            s_ahi, s_alo, s_whi, s_wlo, bias, res, C, M, N, K);
    } else {
        dim3 grid(N / 128, M / 128);
        gemm_ps_kernel<128, 2><<<grid, 256, 79872>>>(
            s_ahi, s_alo, s_whi, s_wlo, bias, res, C, M, N, K);
    }
}

extern "C" void kernel_launch(void* const* d_in, const int* in_sizes, int n_in,
                              void* d_out, int out_size) {
    const int*   ids    = (const int*)d_in[0];
    const float* emb    = (const float*)d_in[1];
    const float* Wq     = (const float*)d_in[2];
    const float* bq     = (const float*)d_in[3];
    const float* Wk     = (const float*)d_in[4];
    const float* bk     = (const float*)d_in[5];
    const float* Wv     = (const float*)d_in[6];
    const float* bv     = (const float*)d_in[7];
    const float* Wo     = (const float*)d_in[8];
    const float* ln1    = (const float*)d_in[9];
    const float* ln2    = (const float*)d_in[10];
    const float* Wg     = (const float*)d_in[11];
    const float* Wu     = (const float*)d_in[12];
    const float* Wd     = (const float*)d_in[13];
    const float* norm_w = (const float*)d_in[14];
    const float* Wlm    = (const float*)d_in[15];
    const float* blm    = (const float*)d_in[16];
    float* out = (float*)d_out;

    float* base = nullptr;
    cudaGetSymbolAddress((void**)&base, g_scratch);
    cudaGetSymbolAddress((void**)&s_ahi, g_ahi);
    cudaGetSymbolAddress((void**)&s_alo, g_alo);
    cudaGetSymbolAddress((void**)&s_whi, g_whi);
    cudaGetSymbolAddress((void**)&s_wlo, g_wlo);

    float* hbuf  = base;
    float* qkv   = base + (size_t)SH;
    float* gbuf  = qkv + (size_t)SQ * NQKV;
    float* ubuf  = gbuf + (size_t)SFF;
    float* bpack = ubuf + (size_t)SFF;

    cudaFuncSetAttribute(attn_kernel, cudaFuncAttributeMaxDynamicSharedMemorySize,
                         ATTN_SMEM);
    cudaFuncSetAttribute(gemm_ps_kernel<128, 2>,
                         cudaFuncAttributeMaxDynamicSharedMemorySize, 79872);
    cudaFuncSetAttribute(gemm_big_kernel,
                         cudaFuncAttributeMaxDynamicSharedMemorySize, BIG_SMEM);

    embed_kernel<<<SH / 4 / 256, 256>>>(ids, emb, hbuf);

    for (int l = 0; l < NLAYER; l++) {
        const float* Wql = Wq + (size_t)l * HID * HID;
        const float* bql = bq + (size_t)l * HID;
        const float* Wkl = Wk + (size_t)l * HID * (NKVH * HDIM);
        const float* bkl = bk + (size_t)l * (NKVH * HDIM);
        const float* Wvl = Wv + (size_t)l * HID * (NKVH * HDIM);
        const float* bvl = bv + (size_t)l * (NKVH * HDIM);
        const float* Wol = Wo + (size_t)l * HID * HID;
        const float* l1  = ln1 + (size_t)l * HID;
        const float* l2  = ln2 + (size_t)l * HID;
        const float* Wgl = Wg + (size_t)l * HID * FFD;
        const float* Wul = Wu + (size_t)l * HID * FFD;
        const float* Wdl = Wd + (size_t)l * FFD * HID;

        // fused QKV projection
        biaspack_kernel<<<NQKV / 256, 256>>>(bql, bkl, bvl, bpack);
        rmsnorm_split_kernel<<<SQ, 256>>>(hbuf, l1, s_ahi, s_alo);
        {   // Wq -> qkv weight cols [0,2048)
            int nT = (int)((size_t)HID * HID / 16);
            split2d_kernel<<<nT / 256, 256>>>(
                Wql, s_whi, s_wlo, HID / 4, NQKV / 4, nT);
        }
        {
            int nT = HID * 1024 / 16;
            splitkv_kernel<<<nT / 256, 256>>>(Wkl, Wvl, s_whi, s_wlo, nT);
        }
        run_gemm(bpack, nullptr, qkv, SQ, NQKV, HID);

        dim3 rgrid(SQ, NHEAD + NKVH);
        rope_kernel<<<rgrid, 64>>>(qkv);

        dim3 agrid(NHEAD, SQ / 64);
        attn_kernel<<<agrid, 256, ATTN_SMEM>>>(qkv, qkv + HID,
                                               qkv + HID + NKVH * HDIM,
                                               s_ahi, s_alo);

        run_split(Wol, (size_t)HID * HID);
        run_gemm(nullptr, hbuf, hbuf, SQ, HID, HID);

        rmsnorm_split_kernel<<<SQ, 256>>>(hbuf, l2, s_ahi, s_alo);
        run_split(Wgl, (size_t)HID * FFD);
        run_gemm(nullptr, nullptr, gbuf, SQ, FFD, HID);
        run_split(Wul, (size_t)HID * FFD);
        run_gemm(nullptr, nullptr, ubuf, SQ, FFD, HID);
        silu_split_kernel<<<SFF / 4 / 256, 256>>>(gbuf, ubuf, s_ahi, s_alo);
        run_split(Wdl, (size_t)FFD * HID);
        run_gemm(nullptr, hbuf, hbuf, SQ, HID, FFD);
    }

    rmsnorm_split_kernel<<<SQ, 256>>>(hbuf, norm_w, s_ahi, s_alo);
    run_split(Wlm, (size_t)HID * VOC);
    run_gemm(blm, nullptr, out, SQ, VOC, HID);
}